// round 7
// baseline (speedup 1.0000x reference)
#include <cuda_runtime.h>

// LatentODE2 R7: R6 (E=8/warp, 1-warp CTAs, f32x2 output-pairs) plus:
//  - dy-reduction HOISTED out of the Euler loop: y = x0 + cs*(sum_s p_s) + 10*cs*b4
//    (y has no feedback into h/z). Butterfly SHFLs drop 400 -> 40 per t-step
//    and leave the per-step critical path.
//  - tanh.approx.f32 on the g/dy path ONLY (no state feedback; error ~2e-5 on y).
//    Exact tanh kept on z/dh (h feedback path, 1000-step accumulation).
//  - __syncwarp right after z-publish so p-accum MUFUs overlap dh-loop LDS.

#define T_STEPS 100
#define D_IN    16
#define H_DIM   32
#define HD_DIM  50
#define EULER   10
#define STEP_F  0.1f
#define DTS_F   (1.0f / 24.0f)

#define E       8
#define GRID    1024        // 8192 / 8, 32-thread CTAs

typedef unsigned long long u64;

__device__ __forceinline__ u64 pk2(float lo, float hi) {
    u64 r; asm("mov.b64 %0, {%1, %2};" : "=l"(r) : "f"(lo), "f"(hi)); return r;
}
__device__ __forceinline__ void up2(u64 v, float& a, float& b) {
    asm("mov.b64 {%0, %1}, %2;" : "=f"(a), "=f"(b) : "l"(v));
}
__device__ __forceinline__ void fma2(u64& d, u64 a, u64 b) {
    asm("fma.rn.f32x2 %0, %1, %2, %0;" : "+l"(d) : "l"(a), "l"(b));
}

__device__ __forceinline__ float my_tanh(float v) {          // exact-ish (state path)
    v = fminf(fmaxf(v, -15.0f), 15.0f);
    float e = __expf(2.0f * v);
    return __fdividef(e - 1.0f, e + 1.0f);
}
__device__ __forceinline__ float tanh_fast(float v) {        // approx (dy path only)
    float r; asm("tanh.approx.f32 %0, %1;" : "=f"(r) : "f"(v)); return r;
}
__device__ __forceinline__ u64 tanh2(u64 v) {
    float a, b; up2(v, a, b);
    return pk2(my_tanh(a), my_tanh(b));
}

__global__ void __launch_bounds__(32, 7)
latentode2_kernel(const float* __restrict__ dt,
                  const float* __restrict__ x,
                  const float* __restrict__ W1, const float* __restrict__ b1,
                  const float* __restrict__ W2, const float* __restrict__ b2,
                  const float* __restrict__ W3, const float* __restrict__ b3,
                  const float* __restrict__ W4, const float* __restrict__ b4,
                  float* __restrict__ out)
{
    // sW1x[k*32+j] = (W1[j][k], W1[j+32][k])                      k<16 (x part)
    // sW13[k*32+j] = (W1[j][16+k], W1[j+32][16+k], W3[j][k], W3[j+32][k])  k<32
    __shared__ float2 sW1x[16 * 32];
    __shared__ float4 sW13[32 * 32];
    // State rows, split: A = elems 0..3 (two f32x2), B = elems 4..7.
    __shared__ ulonglong2 sXA[D_IN],  sXB[D_IN];
    __shared__ ulonglong2 sHA[H_DIM], sHB[H_DIM];
    __shared__ ulonglong2 sZA[HD_DIM], sZB[HD_DIM];

    const int lane = threadIdx.x;

    for (int idx = lane; idx < 16 * 32; idx += 32) {
        int k = idx >> 5, j = idx & 31;
        float hi = (j + 32 < HD_DIM) ? W1[(j + 32) * 48 + k] : 0.0f;
        sW1x[idx] = make_float2(W1[j * 48 + k], hi);
    }
    for (int idx = lane; idx < 32 * 32; idx += 32) {
        int k = idx >> 5, j = idx & 31;
        float w1hi = (j + 32 < HD_DIM) ? W1[(j + 32) * 48 + 16 + k] : 0.0f;
        sW13[idx] = make_float4(W1[j * 48 + 16 + k], w1hi,
                                W3[j * 32 + k], W3[(j + 32) * 32 + k]);
    }

    const int e0 = blockIdx.x * E;

    // W2 row in registers (lane = output k of dh).
    float w2r[HD_DIM];
#pragma unroll
    for (int j = 0; j < HD_DIM; j++) w2r[j] = W2[lane * HD_DIM + j];

    const float b1lo = b1[lane];
    const float b1hi = (lane + 32 < HD_DIM) ? b1[lane + 32] : 0.0f;
    const u64 PB3lo = pk2(b3[lane], b3[lane]);
    const u64 PB3hi = pk2(b3[lane + 32], b3[lane + 32]);
    const float b2s = b2[lane];
    const u64 PB2 = pk2(b2s, b2s);
    const float b4v = b4[0];
    const float w4a = W4[lane];
    const float w4b = W4[lane + 32];

    // h state (8 elems, own row) in registers + SMEM mirror.
    float h0 = 0, h1 = 0, h2 = 0, h3 = 0, h4 = 0, h5 = 0, h6 = 0, h7 = 0;
    sHA[lane] = make_ulonglong2(0ull, 0ull);
    sHB[lane] = make_ulonglong2(0ull, 0ull);
    __syncwarp();

    const float2* dt2 = (const float2*)dt;

#pragma unroll 1
    for (int t = 0; t < T_STEPS; t++) {
        // Stage x rows (lanes 0..15 handle feature = lane).
        if (lane < D_IN) {
            float xv[E];
#pragma unroll
            for (int e = 0; e < E; e++)
                xv[e] = x[((e0 + e) * T_STEPS + t) * D_IN + lane];
            sXA[lane] = make_ulonglong2(pk2(xv[0], xv[1]), pk2(xv[2], xv[3]));
            sXB[lane] = make_ulonglong2(pk2(xv[4], xv[5]), pk2(xv[6], xv[7]));
        }
        float cs[E];
#pragma unroll
        for (int e = 0; e < E; e++) {
            float2 d = dt2[(e0 + e) * T_STEPS + t];
            cs[e] = STEP_F * ((d.y - d.x) * DTS_F);
        }
        __syncwarp();

        // Hoisted: zx = b1 + x @ W1x^T (reused across all 10 Euler steps).
        u64 zxj01 = pk2(b1lo, b1lo), zxj23 = zxj01, zxj45 = zxj01, zxj67 = zxj01;
        u64 zxk01 = pk2(b1hi, b1hi), zxk23 = zxk01, zxk45 = zxk01, zxk67 = zxk01;
#pragma unroll
        for (int k = 0; k < D_IN; k++) {
            ulonglong2 vA = sXA[k], vB = sXB[k];
            float2 w = sW1x[k * 32 + lane];
            u64 wl = pk2(w.x, w.x), wh = pk2(w.y, w.y);
            fma2(zxj01, vA.x, wl); fma2(zxj23, vA.y, wl);
            fma2(zxj45, vB.x, wl); fma2(zxj67, vB.y, wl);
            fma2(zxk01, vA.x, wh); fma2(zxk23, vA.y, wh);
            fma2(zxk45, vB.x, wh); fma2(zxk67, vB.y, wh);
        }

        // Per-lane dy partial sums, accumulated over ALL Euler steps.
        float p0 = 0, p1 = 0, p2 = 0, p3 = 0, p4 = 0, p5 = 0, p6 = 0, p7 = 0;

#pragma unroll 1
        for (int s = 0; s < EULER; s++) {
            u64 zj01 = zxj01, zj23 = zxj23, zj45 = zxj45, zj67 = zxj67;
            u64 zk01 = zxk01, zk23 = zxk23, zk45 = zxk45, zk67 = zxk67;
            u64 gj01 = PB3lo, gj23 = PB3lo, gj45 = PB3lo, gj67 = PB3lo;
            u64 gk01 = PB3hi, gk23 = PB3hi, gk45 = PB3hi, gk67 = PB3hi;

            // Fused: z1 += h @ W1h^T ; g = b3 + h @ W3^T
#pragma unroll
            for (int k = 0; k < H_DIM; k++) {
                ulonglong2 vA = sHA[k], vB = sHB[k];
                float4 w = sW13[k * 32 + lane];
                u64 w1l = pk2(w.x, w.x), w1h = pk2(w.y, w.y);
                u64 w3l = pk2(w.z, w.z), w3h = pk2(w.w, w.w);
                fma2(zj01, vA.x, w1l); fma2(zj23, vA.y, w1l);
                fma2(zj45, vB.x, w1l); fma2(zj67, vB.y, w1l);
                fma2(zk01, vA.x, w1h); fma2(zk23, vA.y, w1h);
                fma2(zk45, vB.x, w1h); fma2(zk67, vB.y, w1h);
                fma2(gj01, vA.x, w3l); fma2(gj23, vA.y, w3l);
                fma2(gj45, vB.x, w3l); fma2(gj67, vB.y, w3l);
                fma2(gk01, vA.x, w3h); fma2(gk23, vA.y, w3h);
                fma2(gk45, vB.x, w3h); fma2(gk67, vB.y, w3h);
            }

            // z = tanh(z1-pre) [exact], publish rows lane and lane+32.
            sZA[lane] = make_ulonglong2(tanh2(zj01), tanh2(zj23));
            sZB[lane] = make_ulonglong2(tanh2(zj45), tanh2(zj67));
            if (lane + 32 < HD_DIM) {
                sZA[lane + 32] = make_ulonglong2(tanh2(zk01), tanh2(zk23));
                sZB[lane + 32] = make_ulonglong2(tanh2(zk45), tanh2(zk67));
            }
            __syncwarp();   // z published; h-loop reads of this step done

            // dy partial accumulation (approx tanh, y-path only -> no feedback).
            {
                float a, b, c, d;
                up2(gj01, a, b); up2(gk01, c, d);
                p0 = fmaf(tanh_fast(a), w4a, fmaf(tanh_fast(c), w4b, p0));
                p1 = fmaf(tanh_fast(b), w4a, fmaf(tanh_fast(d), w4b, p1));
                up2(gj23, a, b); up2(gk23, c, d);
                p2 = fmaf(tanh_fast(a), w4a, fmaf(tanh_fast(c), w4b, p2));
                p3 = fmaf(tanh_fast(b), w4a, fmaf(tanh_fast(d), w4b, p3));
                up2(gj45, a, b); up2(gk45, c, d);
                p4 = fmaf(tanh_fast(a), w4a, fmaf(tanh_fast(c), w4b, p4));
                p5 = fmaf(tanh_fast(b), w4a, fmaf(tanh_fast(d), w4b, p5));
                up2(gj67, a, b); up2(gk67, c, d);
                p6 = fmaf(tanh_fast(a), w4a, fmaf(tanh_fast(c), w4b, p6));
                p7 = fmaf(tanh_fast(b), w4a, fmaf(tanh_fast(d), w4b, p7));
            }

            // dh_pre = b2 + z @ W2^T (out k = lane), W2 row in registers.
            u64 d01 = PB2, d23 = PB2, d45 = PB2, d67 = PB2;
#pragma unroll
            for (int j = 0; j < HD_DIM; j++) {
                ulonglong2 zA = sZA[j], zB = sZB[j];
                u64 wd = pk2(w2r[j], w2r[j]);
                fma2(d01, zA.x, wd); fma2(d23, zA.y, wd);
                fma2(d45, zB.x, wd); fma2(d67, zB.y, wd);
            }

            // h Euler update (exact tanh; state feedback path).
            {
                float a, b;
                up2(d01, a, b); h0 = fmaf(cs[0], my_tanh(a), h0);
                                h1 = fmaf(cs[1], my_tanh(b), h1);
                up2(d23, a, b); h2 = fmaf(cs[2], my_tanh(a), h2);
                                h3 = fmaf(cs[3], my_tanh(b), h3);
                up2(d45, a, b); h4 = fmaf(cs[4], my_tanh(a), h4);
                                h5 = fmaf(cs[5], my_tanh(b), h5);
                up2(d67, a, b); h6 = fmaf(cs[6], my_tanh(a), h6);
                                h7 = fmaf(cs[7], my_tanh(b), h7);
            }

            sHA[lane] = make_ulonglong2(pk2(h0, h1), pk2(h2, h3));
            sHB[lane] = make_ulonglong2(pk2(h4, h5), pk2(h6, h7));
            __syncwarp();
        }

        // One butterfly reduction per t-step (was one per Euler step).
#pragma unroll
        for (int off = 16; off > 0; off >>= 1) {
            p0 += __shfl_xor_sync(0xffffffffu, p0, off);
            p1 += __shfl_xor_sync(0xffffffffu, p1, off);
            p2 += __shfl_xor_sync(0xffffffffu, p2, off);
            p3 += __shfl_xor_sync(0xffffffffu, p3, off);
            p4 += __shfl_xor_sync(0xffffffffu, p4, off);
            p5 += __shfl_xor_sync(0xffffffffu, p5, off);
            p6 += __shfl_xor_sync(0xffffffffu, p6, off);
            p7 += __shfl_xor_sync(0xffffffffu, p7, off);
        }

        // y_e = x0_e + cs_e * (P_e + EULER*b4); lanes 0..7 write out.
        {
            float x0A, x1A, x2A, x3A, x4A, x5A, x6A, x7A;
            { ulonglong2 v = sXA[0]; up2(v.x, x0A, x1A); up2(v.y, x2A, x3A); }
            { ulonglong2 v = sXB[0]; up2(v.x, x4A, x5A); up2(v.y, x6A, x7A); }
            const float eb4 = (float)EULER * b4v;
            float yv = fmaf(cs[0], p0 + eb4, x0A);
            if (lane == 1) yv = fmaf(cs[1], p1 + eb4, x1A);
            if (lane == 2) yv = fmaf(cs[2], p2 + eb4, x2A);
            if (lane == 3) yv = fmaf(cs[3], p3 + eb4, x3A);
            if (lane == 4) yv = fmaf(cs[4], p4 + eb4, x4A);
            if (lane == 5) yv = fmaf(cs[5], p5 + eb4, x5A);
            if (lane == 6) yv = fmaf(cs[6], p6 + eb4, x6A);
            if (lane == 7) yv = fmaf(cs[7], p7 + eb4, x7A);
            if (lane < E) out[(e0 + lane) * T_STEPS + t] = yv;
        }
        __syncwarp();   // sX reads done before next t overwrites
    }
}

extern "C" void kernel_launch(void* const* d_in, const int* in_sizes, int n_in,
                              void* d_out, int out_size) {
    (void)in_sizes; (void)n_in; (void)out_size;
    const float* dt = (const float*)d_in[0];
    const float* x  = (const float*)d_in[1];
    const float* W1 = (const float*)d_in[2];
    const float* b1 = (const float*)d_in[3];
    const float* W2 = (const float*)d_in[4];
    const float* b2 = (const float*)d_in[5];
    const float* W3 = (const float*)d_in[6];
    const float* b3 = (const float*)d_in[7];
    const float* W4 = (const float*)d_in[8];
    const float* b4 = (const float*)d_in[9];
    float* out = (float*)d_out;

    latentode2_kernel<<<GRID, 32>>>(
        dt, x, W1, b1, W2, b2, W3, b3, W4, b4, out);
}

// round 8
// speedup vs baseline: 1.2614x; 1.2614x over previous
#include <cuda_runtime.h>

// LatentODE2 R8: R6 structure (E=8/warp, 1-warp CTAs, f32x2 output-lane pairs,
// zx-hoist, W2-in-regs) with:
//  - tanh.approx.f32 on ALL tanh sites (1 instr / 1 MUFU vs 7 instr / 2 MUFU).
//    Feedback-path error ~2e-4 abs on h over 1000 steps; y rel err ~1e-4 << 1e-3.
//  - dy reduction hoisted out of the Euler loop (R7 algebra: y has no feedback),
//    now affordable register-wise thanks to the freed tanh temporaries.

#define T_STEPS 100
#define D_IN    16
#define H_DIM   32
#define HD_DIM  50
#define EULER   10
#define STEP_F  0.1f
#define DTS_F   (1.0f / 24.0f)

#define E       8
#define GRID    1024        // 8192 / 8, 32-thread CTAs

typedef unsigned long long u64;

__device__ __forceinline__ u64 pk2(float lo, float hi) {
    u64 r; asm("mov.b64 %0, {%1, %2};" : "=l"(r) : "f"(lo), "f"(hi)); return r;
}
__device__ __forceinline__ void up2(u64 v, float& a, float& b) {
    asm("mov.b64 {%0, %1}, %2;" : "=f"(a), "=f"(b) : "l"(v));
}
__device__ __forceinline__ void fma2(u64& d, u64 a, u64 b) {
    asm("fma.rn.f32x2 %0, %1, %2, %0;" : "+l"(d) : "l"(a), "l"(b));
}

__device__ __forceinline__ float tanh_fast(float v) {
    float r; asm("tanh.approx.f32 %0, %1;" : "=f"(r) : "f"(v)); return r;
}
__device__ __forceinline__ u64 tanh2(u64 v) {
    float a, b; up2(v, a, b);
    return pk2(tanh_fast(a), tanh_fast(b));
}

__global__ void __launch_bounds__(32, 7)
latentode2_kernel(const float* __restrict__ dt,
                  const float* __restrict__ x,
                  const float* __restrict__ W1, const float* __restrict__ b1,
                  const float* __restrict__ W2, const float* __restrict__ b2,
                  const float* __restrict__ W3, const float* __restrict__ b3,
                  const float* __restrict__ W4, const float* __restrict__ b4,
                  float* __restrict__ out)
{
    // sW1x[k*32+j] = (W1[j][k], W1[j+32][k])                      k<16 (x part)
    // sW13[k*32+j] = (W1[j][16+k], W1[j+32][16+k], W3[j][k], W3[j+32][k])  k<32
    __shared__ float2 sW1x[16 * 32];
    __shared__ float4 sW13[32 * 32];
    // State rows, split: A = elems 0..3 (two f32x2), B = elems 4..7.
    __shared__ ulonglong2 sXA[D_IN],  sXB[D_IN];
    __shared__ ulonglong2 sHA[H_DIM], sHB[H_DIM];
    __shared__ ulonglong2 sZA[HD_DIM], sZB[HD_DIM];

    const int lane = threadIdx.x;

    for (int idx = lane; idx < 16 * 32; idx += 32) {
        int k = idx >> 5, j = idx & 31;
        float hi = (j + 32 < HD_DIM) ? W1[(j + 32) * 48 + k] : 0.0f;
        sW1x[idx] = make_float2(W1[j * 48 + k], hi);
    }
    for (int idx = lane; idx < 32 * 32; idx += 32) {
        int k = idx >> 5, j = idx & 31;
        float w1hi = (j + 32 < HD_DIM) ? W1[(j + 32) * 48 + 16 + k] : 0.0f;
        sW13[idx] = make_float4(W1[j * 48 + 16 + k], w1hi,
                                W3[j * 32 + k], W3[(j + 32) * 32 + k]);
    }

    const int e0 = blockIdx.x * E;

    // W2 row in registers (lane = output k of dh).
    float w2r[HD_DIM];
#pragma unroll
    for (int j = 0; j < HD_DIM; j++) w2r[j] = W2[lane * HD_DIM + j];

    const float b1lo = b1[lane];
    const float b1hi = (lane + 32 < HD_DIM) ? b1[lane + 32] : 0.0f;
    const u64 PB3lo = pk2(b3[lane], b3[lane]);
    const u64 PB3hi = pk2(b3[lane + 32], b3[lane + 32]);
    const float b2s = b2[lane];
    const u64 PB2 = pk2(b2s, b2s);
    const float b4v = b4[0];
    const float w4a = W4[lane];
    const float w4b = W4[lane + 32];

    // h state (8 elems, own row) in registers + SMEM mirror.
    float h0 = 0, h1 = 0, h2 = 0, h3 = 0, h4 = 0, h5 = 0, h6 = 0, h7 = 0;
    sHA[lane] = make_ulonglong2(0ull, 0ull);
    sHB[lane] = make_ulonglong2(0ull, 0ull);
    __syncwarp();

    const float2* dt2 = (const float2*)dt;

#pragma unroll 1
    for (int t = 0; t < T_STEPS; t++) {
        // Stage x rows (lanes 0..15 handle feature = lane).
        if (lane < D_IN) {
            float xv[E];
#pragma unroll
            for (int e = 0; e < E; e++)
                xv[e] = x[((e0 + e) * T_STEPS + t) * D_IN + lane];
            sXA[lane] = make_ulonglong2(pk2(xv[0], xv[1]), pk2(xv[2], xv[3]));
            sXB[lane] = make_ulonglong2(pk2(xv[4], xv[5]), pk2(xv[6], xv[7]));
        }
        float cs[E];
#pragma unroll
        for (int e = 0; e < E; e++) {
            float2 d = dt2[(e0 + e) * T_STEPS + t];
            cs[e] = STEP_F * ((d.y - d.x) * DTS_F);
        }
        __syncwarp();

        // Hoisted: zx = b1 + x @ W1x^T (reused across all 10 Euler steps).
        u64 zxj01 = pk2(b1lo, b1lo), zxj23 = zxj01, zxj45 = zxj01, zxj67 = zxj01;
        u64 zxk01 = pk2(b1hi, b1hi), zxk23 = zxk01, zxk45 = zxk01, zxk67 = zxk01;
#pragma unroll
        for (int k = 0; k < D_IN; k++) {
            ulonglong2 vA = sXA[k], vB = sXB[k];
            float2 w = sW1x[k * 32 + lane];
            u64 wl = pk2(w.x, w.x), wh = pk2(w.y, w.y);
            fma2(zxj01, vA.x, wl); fma2(zxj23, vA.y, wl);
            fma2(zxj45, vB.x, wl); fma2(zxj67, vB.y, wl);
            fma2(zxk01, vA.x, wh); fma2(zxk23, vA.y, wh);
            fma2(zxk45, vB.x, wh); fma2(zxk67, vB.y, wh);
        }

        // Per-lane dy partial sums, accumulated over ALL Euler steps.
        float p0 = 0, p1 = 0, p2 = 0, p3 = 0, p4 = 0, p5 = 0, p6 = 0, p7 = 0;

#pragma unroll 1
        for (int s = 0; s < EULER; s++) {
            u64 zj01 = zxj01, zj23 = zxj23, zj45 = zxj45, zj67 = zxj67;
            u64 zk01 = zxk01, zk23 = zxk23, zk45 = zxk45, zk67 = zxk67;
            u64 gj01 = PB3lo, gj23 = PB3lo, gj45 = PB3lo, gj67 = PB3lo;
            u64 gk01 = PB3hi, gk23 = PB3hi, gk45 = PB3hi, gk67 = PB3hi;

            // Fused: z1 += h @ W1h^T ; g = b3 + h @ W3^T
#pragma unroll
            for (int k = 0; k < H_DIM; k++) {
                ulonglong2 vA = sHA[k], vB = sHB[k];
                float4 w = sW13[k * 32 + lane];
                u64 w1l = pk2(w.x, w.x), w1h = pk2(w.y, w.y);
                u64 w3l = pk2(w.z, w.z), w3h = pk2(w.w, w.w);
                fma2(zj01, vA.x, w1l); fma2(zj23, vA.y, w1l);
                fma2(zj45, vB.x, w1l); fma2(zj67, vB.y, w1l);
                fma2(zk01, vA.x, w1h); fma2(zk23, vA.y, w1h);
                fma2(zk45, vB.x, w1h); fma2(zk67, vB.y, w1h);
                fma2(gj01, vA.x, w3l); fma2(gj23, vA.y, w3l);
                fma2(gj45, vB.x, w3l); fma2(gj67, vB.y, w3l);
                fma2(gk01, vA.x, w3h); fma2(gk23, vA.y, w3h);
                fma2(gk45, vB.x, w3h); fma2(gk67, vB.y, w3h);
            }

            // z = tanh(z1-pre), publish rows lane and lane+32.
            sZA[lane] = make_ulonglong2(tanh2(zj01), tanh2(zj23));
            sZB[lane] = make_ulonglong2(tanh2(zj45), tanh2(zj67));
            if (lane + 32 < HD_DIM) {
                sZA[lane + 32] = make_ulonglong2(tanh2(zk01), tanh2(zk23));
                sZB[lane + 32] = make_ulonglong2(tanh2(zk45), tanh2(zk67));
            }
            __syncwarp();   // z published; h-loop reads of this step done

            // dy partial accumulation (no reduction here; y has no feedback).
            {
                float a, b, c, d;
                up2(gj01, a, b); up2(gk01, c, d);
                p0 = fmaf(tanh_fast(a), w4a, fmaf(tanh_fast(c), w4b, p0));
                p1 = fmaf(tanh_fast(b), w4a, fmaf(tanh_fast(d), w4b, p1));
                up2(gj23, a, b); up2(gk23, c, d);
                p2 = fmaf(tanh_fast(a), w4a, fmaf(tanh_fast(c), w4b, p2));
                p3 = fmaf(tanh_fast(b), w4a, fmaf(tanh_fast(d), w4b, p3));
                up2(gj45, a, b); up2(gk45, c, d);
                p4 = fmaf(tanh_fast(a), w4a, fmaf(tanh_fast(c), w4b, p4));
                p5 = fmaf(tanh_fast(b), w4a, fmaf(tanh_fast(d), w4b, p5));
                up2(gj67, a, b); up2(gk67, c, d);
                p6 = fmaf(tanh_fast(a), w4a, fmaf(tanh_fast(c), w4b, p6));
                p7 = fmaf(tanh_fast(b), w4a, fmaf(tanh_fast(d), w4b, p7));
            }

            // dh_pre = b2 + z @ W2^T (out k = lane), W2 row in registers.
            u64 d01 = PB2, d23 = PB2, d45 = PB2, d67 = PB2;
#pragma unroll
            for (int j = 0; j < HD_DIM; j++) {
                ulonglong2 zA = sZA[j], zB = sZB[j];
                u64 wd = pk2(w2r[j], w2r[j]);
                fma2(d01, zA.x, wd); fma2(d23, zA.y, wd);
                fma2(d45, zB.x, wd); fma2(d67, zB.y, wd);
            }

            // h Euler update.
            {
                float a, b;
                up2(d01, a, b); h0 = fmaf(cs[0], tanh_fast(a), h0);
                                h1 = fmaf(cs[1], tanh_fast(b), h1);
                up2(d23, a, b); h2 = fmaf(cs[2], tanh_fast(a), h2);
                                h3 = fmaf(cs[3], tanh_fast(b), h3);
                up2(d45, a, b); h4 = fmaf(cs[4], tanh_fast(a), h4);
                                h5 = fmaf(cs[5], tanh_fast(b), h5);
                up2(d67, a, b); h6 = fmaf(cs[6], tanh_fast(a), h6);
                                h7 = fmaf(cs[7], tanh_fast(b), h7);
            }

            sHA[lane] = make_ulonglong2(pk2(h0, h1), pk2(h2, h3));
            sHB[lane] = make_ulonglong2(pk2(h4, h5), pk2(h6, h7));
            __syncwarp();
        }

        // One butterfly reduction per t-step (was one per Euler step).
#pragma unroll
        for (int off = 16; off > 0; off >>= 1) {
            p0 += __shfl_xor_sync(0xffffffffu, p0, off);
            p1 += __shfl_xor_sync(0xffffffffu, p1, off);
            p2 += __shfl_xor_sync(0xffffffffu, p2, off);
            p3 += __shfl_xor_sync(0xffffffffu, p3, off);
            p4 += __shfl_xor_sync(0xffffffffu, p4, off);
            p5 += __shfl_xor_sync(0xffffffffu, p5, off);
            p6 += __shfl_xor_sync(0xffffffffu, p6, off);
            p7 += __shfl_xor_sync(0xffffffffu, p7, off);
        }

        // y_e = x0_e + cs_e * (P_e + EULER*b4); lanes 0..7 write out.
        {
            float x0A, x1A, x2A, x3A, x4A, x5A, x6A, x7A;
            { ulonglong2 v = sXA[0]; up2(v.x, x0A, x1A); up2(v.y, x2A, x3A); }
            { ulonglong2 v = sXB[0]; up2(v.x, x4A, x5A); up2(v.y, x6A, x7A); }
            const float eb4 = (float)EULER * b4v;
            float yv = fmaf(cs[0], p0 + eb4, x0A);
            if (lane == 1) yv = fmaf(cs[1], p1 + eb4, x1A);
            if (lane == 2) yv = fmaf(cs[2], p2 + eb4, x2A);
            if (lane == 3) yv = fmaf(cs[3], p3 + eb4, x3A);
            if (lane == 4) yv = fmaf(cs[4], p4 + eb4, x4A);
            if (lane == 5) yv = fmaf(cs[5], p5 + eb4, x5A);
            if (lane == 6) yv = fmaf(cs[6], p6 + eb4, x6A);
            if (lane == 7) yv = fmaf(cs[7], p7 + eb4, x7A);
            if (lane < E) out[(e0 + lane) * T_STEPS + t] = yv;
        }
        __syncwarp();   // sX reads done before next t overwrites
    }
}

extern "C" void kernel_launch(void* const* d_in, const int* in_sizes, int n_in,
                              void* d_out, int out_size) {
    (void)in_sizes; (void)n_in; (void)out_size;
    const float* dt = (const float*)d_in[0];
    const float* x  = (const float*)d_in[1];
    const float* W1 = (const float*)d_in[2];
    const float* b1 = (const float*)d_in[3];
    const float* W2 = (const float*)d_in[4];
    const float* b2 = (const float*)d_in[5];
    const float* W3 = (const float*)d_in[6];
    const float* b3 = (const float*)d_in[7];
    const float* W4 = (const float*)d_in[8];
    const float* b4 = (const float*)d_in[9];
    float* out = (float*)d_out;

    latentode2_kernel<<<GRID, 32>>>(
        dt, x, W1, b1, W2, b2, W3, b3, W4, b4, out);
}